// round 14
// baseline (speedup 1.0000x reference)
#include <cuda_runtime.h>
#include <cuda_bf16.h>
#include <mma.h>
using namespace nvcuda;

#define N_    4096
#define C_    128
#define H_    128
#define O_    64
#define E_    65536
#define WPR   128                 // 32-bit words per mask row (4096/32)
#define HALF_ 8388608             // N*N/2 for threefry pairing
#define TOPK_ 10
#define KSPLIT 8                  // gemm2 split-K factor
#define NT_   32                  // 128-tiles per dim
#define NTRI  528                 // NT_*(NT_+1)/2
#define TFB   32768               // threefry blocks in mega kernel

// ---------------- scratch (static device globals; no allocation) ----------------
static __device__ unsigned       g_Abits[N_ * WPR];          // 2 MB adjacency bitmask
static __device__ unsigned       g_Mbits[N_ * WPR];          // 2 MB keep-mask bitmask
static __device__ float          g_big[(size_t)N_ * N_];     // 64 MB: sim; later gemm2 partials
static __device__ __nv_bfloat16  g_xnb[N_ * C_];             // xn in bf16
static __device__ __nv_bfloat16  g_aggT[(size_t)C_ * N_];    // agg^T bf16 [C][N]
static __device__ float          g_Ax [N_ * C_];
static __device__ float          g_A2x[N_ * C_];
static __device__ int            g_topk[N_ * TOPK_];
static __device__ float          g_deg[N_];

// ---------------- fused: scatter edges (blocks 0..255) + rownorm (256..767) ----------
// edge_index is int32 (JAX x64 disabled downgrades int64 -> int32), layout [2, E]
__global__ void __launch_bounds__(256) k_pre(const int* __restrict__ ei,
                                             const float* __restrict__ x) {
    if (blockIdx.x < E_ / 256) {
        int i = blockIdx.x * 256 + threadIdx.x;
        int s = ei[i];
        int d = ei[E_ + i];
        atomicOr(&g_Abits[s * WPR + (d >> 5)], 1u << (d & 31));
        return;
    }
    int g    = (blockIdx.x - E_ / 256) * 256 + threadIdx.x;
    int row  = g >> 5;
    int lane = g & 31;
    if (row >= N_) return;
    const float4* xr = reinterpret_cast<const float4*>(x + (size_t)row * C_);
    float4 v = xr[lane];
    float s = v.x * v.x + v.y * v.y + v.z * v.z + v.w * v.w;
    #pragma unroll
    for (int o = 16; o; o >>= 1) s += __shfl_xor_sync(0xffffffffu, s, o);
    float inv = 1.0f / (sqrtf(s) + 1e-8f);
    __nv_bfloat162 p0 = __floats2bfloat162_rn(v.x * inv, v.y * inv);
    __nv_bfloat162 p1 = __floats2bfloat162_rn(v.z * inv, v.w * inv);
    __nv_bfloat162* dst = reinterpret_cast<__nv_bfloat162*>(g_xnb + (size_t)row * C_ + lane * 4);
    dst[0] = p0;
    dst[1] = p1;
}

// ---------------- GEMM1 (symmetric): sim = xnb @ xnb^T, upper-tri tiles only ---------
#define G1PAD 16
__global__ void __launch_bounds__(256, 2) k_gemm1_wmma() {
    __shared__ __nv_bfloat16 As[128][128 + G1PAD];
    __shared__ __nv_bfloat16 Bs[128][128 + G1PAD];
    int tid = threadIdx.x;

    int idx = blockIdx.x;
    int bm = 0;
    while ((bm + 1) * NT_ - ((bm + 1) * bm) / 2 <= idx) bm++;
    int bn = bm + idx - (bm * NT_ - (bm * (bm - 1)) / 2);
    int m0 = bm * 128, n0 = bn * 128;

    #pragma unroll
    for (int it = 0; it < 8; it++) {
        int chunk = tid + 256 * it;
        int r = chunk >> 4, c8 = chunk & 15;
        *reinterpret_cast<uint4*>(&As[r][c8 * 8]) =
            *reinterpret_cast<const uint4*>(g_xnb + (size_t)(m0 + r) * C_ + c8 * 8);
        *reinterpret_cast<uint4*>(&Bs[r][c8 * 8]) =
            *reinterpret_cast<const uint4*>(g_xnb + (size_t)(n0 + r) * C_ + c8 * 8);
    }
    __syncthreads();

    int w = tid >> 5;
    int wm = w >> 2, wn = w & 3;
    wmma::fragment<wmma::accumulator, 16, 16, 16, float> c[4][2];
    #pragma unroll
    for (int i = 0; i < 4; i++)
        #pragma unroll
        for (int j = 0; j < 2; j++) wmma::fill_fragment(c[i][j], 0.0f);

    #pragma unroll
    for (int kk = 0; kk < 8; kk++) {
        wmma::fragment<wmma::matrix_a, 16, 16, 16, __nv_bfloat16, wmma::row_major> a[4];
        wmma::fragment<wmma::matrix_b, 16, 16, 16, __nv_bfloat16, wmma::col_major> b[2];
        #pragma unroll
        for (int i = 0; i < 4; i++)
            wmma::load_matrix_sync(a[i], &As[wm * 64 + i * 16][kk * 16], 128 + G1PAD);
        #pragma unroll
        for (int j = 0; j < 2; j++)
            wmma::load_matrix_sync(b[j], &Bs[wn * 32 + j * 16][kk * 16], 128 + G1PAD);
        #pragma unroll
        for (int i = 0; i < 4; i++)
            #pragma unroll
            for (int j = 0; j < 2; j++) wmma::mma_sync(c[i][j], a[i], b[j], c[i][j]);
    }
    #pragma unroll
    for (int i = 0; i < 4; i++)
        #pragma unroll
        for (int j = 0; j < 2; j++) {
            int mr = m0 + wm * 64 + i * 16;
            int nc = n0 + wn * 32 + j * 16;
            wmma::store_matrix_sync(g_big + (size_t)mr * N_ + nc, c[i][j], N_,
                                    wmma::mem_row_major);
            if (bm != bn)
                wmma::store_matrix_sync(g_big + (size_t)nc * N_ + mr, c[i][j], N_,
                                        wmma::mem_col_major);
        }
}

// ---------------- helpers ----------------
__device__ __forceinline__ unsigned ford(float f) {
    unsigned u = __float_as_uint(f);
    return (u & 0x80000000u) ? ~u : (u | 0x80000000u);
}

__device__ __forceinline__ void threefry(unsigned c0, unsigned c1, unsigned& o0, unsigned& o1) {
    const unsigned k0 = 0u, k1 = 42u, k2 = 0u ^ 42u ^ 0x1BD11BDAu;
    unsigned x0 = c0 + k0, x1 = c1 + k1;
    #define TF_R(r) { x0 += x1; x1 = __funnelshift_l(x1, x1, (r)); x1 ^= x0; }
    TF_R(13) TF_R(15) TF_R(26) TF_R(6)   x0 += k1; x1 += k2 + 1u;
    TF_R(17) TF_R(29) TF_R(16) TF_R(24)  x0 += k2; x1 += k0 + 2u;
    TF_R(13) TF_R(15) TF_R(26) TF_R(6)   x0 += k0; x1 += k1 + 3u;
    TF_R(17) TF_R(29) TF_R(16) TF_R(24)  x0 += k1; x1 += k2 + 4u;
    TF_R(13) TF_R(15) TF_R(26) TF_R(6)   x0 += k2; x1 += k0 + 5u;
    #undef TF_R
    o0 = x0; o1 = x1;
}

__device__ __forceinline__ unsigned long long umax64(unsigned long long a, unsigned long long b) {
    return a > b ? a : b;
}

// 2-rows-per-block sparse A*V accumulate (256 threads: halves are symmetric)
__device__ __forceinline__ void spmm_2row(int rowbase, const unsigned* __restrict__ bits,
                                          const float* __restrict__ V, float* __restrict__ out,
                                          unsigned short (*nbr)[N_], int (*wsum)[4]) {
    int tid  = threadIdx.x;
    int half = tid >> 7;           // 0/1
    int wtid = tid & 127;          // word/column index within row
    int row  = rowbase + half;
    int lane = tid & 31;
    int wih  = (tid >> 5) & 3;     // warp index within half

    unsigned word = bits[row * WPR + wtid];
    int cnt = __popc(word);
    int inc = cnt;
    #pragma unroll
    for (int o = 1; o < 32; o <<= 1) {
        int v = __shfl_up_sync(0xffffffffu, inc, o);
        if (lane >= o) inc += v;
    }
    if (lane == 31) wsum[half][wih] = inc;
    __syncthreads();
    int base = 0;
    #pragma unroll
    for (int i = 0; i < 4; i++) if (i < wih) base += wsum[half][i];
    int off = base + inc - cnt;
    unsigned b = word;
    while (b) {
        int t = __ffs(b) - 1;
        b &= b - 1;
        nbr[half][off++] = (unsigned short)((wtid << 5) + t);
    }
    int nn = wsum[half][0] + wsum[half][1] + wsum[half][2] + wsum[half][3];
    __syncthreads();

    float a0 = 0.f, a1 = 0.f, a2 = 0.f, a3 = 0.f;
    int i = 0;
    for (; i + 4 <= nn; i += 4) {
        int j0 = nbr[half][i], j1 = nbr[half][i + 1], j2 = nbr[half][i + 2], j3 = nbr[half][i + 3];
        a0 += V[(size_t)j0 * C_ + wtid];
        a1 += V[(size_t)j1 * C_ + wtid];
        a2 += V[(size_t)j2 * C_ + wtid];
        a3 += V[(size_t)j3 * C_ + wtid];
    }
    for (; i < nn; i++) a0 += V[(size_t)nbr[half][i] * C_ + wtid];
    out[(size_t)row * C_ + wtid] = (a0 + a1) + (a2 + a3);
}

// ---------------- mega kernel: threefry + topk + spmm1 (all independent) -------------
__global__ void __launch_bounds__(256) k_big(const float* __restrict__ sim,
                                             const float* __restrict__ x) {
    __shared__ unsigned long long cand[8 * TOPK_];
    __shared__ unsigned short nbr[2][N_];
    __shared__ int wsum[2][4];

    if (blockIdx.x < TFB) {
        // ---- threefry: pure ALU ----
        int t = blockIdx.x * 256 + threadIdx.x;          // 0 .. HALF_-1
        unsigned o0, o1;
        threefry((unsigned)t, (unsigned)t + (unsigned)HALF_, o0, o1);
        unsigned m0 = __ballot_sync(0xffffffffu, !(o0 >> 31));
        unsigned m1 = __ballot_sync(0xffffffffu, !(o1 >> 31));
        int lane = threadIdx.x & 31;
        int wbase = t >> 5;
        if (lane == 0)      g_Mbits[wbase] = m0;
        else if (lane == 1) g_Mbits[(HALF_ >> 5) + wbase] = m1;
        return;
    }
    if (blockIdx.x < TFB + N_) {
        // ---- topk: per-warp top-10, then single-warp merge of 80 candidates ----
        int row  = blockIdx.x - TFB;
        int tid  = threadIdx.x;
        int w    = tid >> 5;
        int lane = tid & 31;

        unsigned long long key[16];
        #pragma unroll
        for (int i = 0; i < 16; i++) {
            int j = w * 512 + i * 32 + lane;
            float v = sim[(size_t)row * N_ + j];
            key[i] = ((unsigned long long)ford(v) << 32) | (unsigned)(N_ - 1 - j);
        }
        #pragma unroll
        for (int p = 0; p < TOPK_; p++) {
            unsigned long long m = 0ull;
            #pragma unroll
            for (int i = 0; i < 16; i++) m = umax64(m, key[i]);
            #pragma unroll
            for (int o = 16; o; o >>= 1)
                m = umax64(m, __shfl_xor_sync(0xffffffffu, m, o));
            if (lane == 0) cand[w * TOPK_ + p] = m;
            #pragma unroll
            for (int i = 0; i < 16; i++) if (key[i] == m) key[i] = 0ull;
        }
        __syncthreads();
        if (w == 0) {
            unsigned long long c0 = cand[lane];              // 0..31
            unsigned long long c1 = cand[lane + 32];         // 32..63
            unsigned long long c2 = (lane < 16) ? cand[lane + 64] : 0ull;  // 64..79
            #pragma unroll
            for (int p = 0; p < TOPK_; p++) {
                unsigned long long m = umax64(c0, umax64(c1, c2));
                #pragma unroll
                for (int o = 16; o; o >>= 1)
                    m = umax64(m, __shfl_xor_sync(0xffffffffu, m, o));
                if (lane == 0) g_topk[row * TOPK_ + p] = (N_ - 1) - (int)(m & 0xffffffffull);
                if (c0 == m) c0 = 0ull;
                if (c1 == m) c1 = 0ull;
                if (c2 == m) c2 = 0ull;
            }
        }
        return;
    }
    // ---- spmm1: Ax = A @ x ----
    spmm_2row((blockIdx.x - (TFB + N_)) * 2, g_Abits, x, g_Ax, nbr, wsum);
}

// ---------------- mid kernel: spmm2 (blocks 0..2047) + or_deg (2048..6143) -----------
__global__ void __launch_bounds__(256) k_mid() {
    __shared__ unsigned short nbr[2][N_];
    __shared__ int wsum[2][4];
    if (blockIdx.x < N_ / 2) {
        spmm_2row(blockIdx.x * 2, g_Abits, g_Ax, g_A2x, nbr, wsum);
        return;
    }
    // or_deg: OR top-k bits into Mbits + row degree (first 128 threads active)
    int row = blockIdx.x - N_ / 2, tid = threadIdx.x;
    if (tid < 128) {
        int lane = tid & 31, w = tid >> 5;
        unsigned wd = g_Mbits[row * WPR + tid];
        #pragma unroll
        for (int p = 0; p < TOPK_; p++) {
            int j = g_topk[row * TOPK_ + p];
            if ((j >> 5) == tid) wd |= 1u << (j & 31);
        }
        g_Mbits[row * WPR + tid] = wd;
        int c = __popc(wd);
        #pragma unroll
        for (int o = 16; o; o >>= 1) c += __shfl_xor_sync(0xffffffffu, c, o);
        if (lane == 0) wsum[0][w] = c;
    }
    __syncthreads();
    if (tid == 0) g_deg[row] = (float)(wsum[0][0] + wsum[0][1] + wsum[0][2] + wsum[0][3]);
}

// ---------------- aggT[c][n] = bf16(a0*x + a1*Ax + a2*A2x)  (fused transpose) ---------
__global__ void __launch_bounds__(256) k_aggT(const float* __restrict__ x,
                                              const float* __restrict__ alpha) {
    __shared__ float t[32][33];
    int bx = blockIdx.x & 3, by = blockIdx.x >> 2;     // (C_/32, N_/32)
    int c0 = bx * 32, r0 = by * 32;
    int tx = threadIdx.x & 31, ty = threadIdx.x >> 5;  // 32 x 8
    float a0 = __ldg(&alpha[0]), a1 = __ldg(&alpha[1]), a2 = __ldg(&alpha[2]);
    #pragma unroll
    for (int i = 0; i < 4; i++) {
        size_t idx = (size_t)(r0 + ty + 8 * i) * C_ + c0 + tx;
        t[ty + 8 * i][tx] = a0 * x[idx] + a1 * g_Ax[idx] + a2 * g_A2x[idx];
    }
    __syncthreads();
    #pragma unroll
    for (int i = 0; i < 4; i++)
        g_aggT[(size_t)(c0 + ty + 8 * i) * N_ + r0 + tx] =
            __float2bfloat16(t[tx][ty + 8 * i]);
}

// ---------------- GEMM2 split-K with on-the-fly bf16 mask expansion ------------------
#define G2PAD 16
__global__ void __launch_bounds__(256, 2) k_gemm2_wmma() {
    __shared__ __nv_bfloat16 As[128][64 + G2PAD];
    __shared__ __nv_bfloat16 Bs[128][64 + G2PAD];
    int tid = threadIdx.x;
    int split = blockIdx.x;
    int m0 = blockIdx.y * 128;
    int kbase = split * (N_ / KSPLIT);
    int w = tid >> 5;
    int wm = w >> 2, wn = w & 3;
    int er = tid >> 1, eh = tid & 1;

    wmma::fragment<wmma::accumulator, 16, 16, 16, float> c[4][2];
    #pragma unroll
    for (int i = 0; i < 4; i++)
        #pragma unroll
        for (int j = 0; j < 2; j++) wmma::fill_fragment(c[i][j], 0.0f);

    for (int k0 = kbase; k0 < kbase + N_ / KSPLIT; k0 += 64) {
        {
            unsigned wd = g_Mbits[(m0 + er) * WPR + (k0 >> 5) + eh];
            __nv_bfloat16* dst = &As[er][eh * 32];
            #pragma unroll
            for (int gq = 0; gq < 4; gq++) {
                uint4 v;
                unsigned b = wd >> (gq * 8);
                v.x = ((b      & 1u) ? 0x3F80u : 0u) | (((b >> 1) & 1u) ? 0x3F800000u : 0u);
                v.y = (((b >> 2) & 1u) ? 0x3F80u : 0u) | (((b >> 3) & 1u) ? 0x3F800000u : 0u);
                v.z = (((b >> 4) & 1u) ? 0x3F80u : 0u) | (((b >> 5) & 1u) ? 0x3F800000u : 0u);
                v.w = (((b >> 6) & 1u) ? 0x3F80u : 0u) | (((b >> 7) & 1u) ? 0x3F800000u : 0u);
                reinterpret_cast<uint4*>(dst)[gq] = v;
            }
        }
        #pragma unroll
        for (int it = 0; it < 4; it++) {
            int chunk = tid + 256 * it;
            int r = chunk >> 3, c8 = chunk & 7;
            *reinterpret_cast<uint4*>(&Bs[r][c8 * 8]) =
                *reinterpret_cast<const uint4*>(g_aggT + (size_t)r * N_ + k0 + c8 * 8);
        }
        __syncthreads();
        #pragma unroll
        for (int kk = 0; kk < 4; kk++) {
            wmma::fragment<wmma::matrix_a, 16, 16, 16, __nv_bfloat16, wmma::row_major> a[4];
            wmma::fragment<wmma::matrix_b, 16, 16, 16, __nv_bfloat16, wmma::col_major> b[2];
            #pragma unroll
            for (int i = 0; i < 4; i++)
                wmma::load_matrix_sync(a[i], &As[wm * 64 + i * 16][kk * 16], 64 + G2PAD);
            #pragma unroll
            for (int j = 0; j < 2; j++)
                wmma::load_matrix_sync(b[j], &Bs[wn * 32 + j * 16][kk * 16], 64 + G2PAD);
            #pragma unroll
            for (int i = 0; i < 4; i++)
                #pragma unroll
                for (int j = 0; j < 2; j++) wmma::mma_sync(c[i][j], a[i], b[j], c[i][j]);
        }
        __syncthreads();
    }
    float* dst = g_big + (size_t)split * (N_ * C_);
    #pragma unroll
    for (int i = 0; i < 4; i++)
        #pragma unroll
        for (int j = 0; j < 2; j++)
            wmma::store_matrix_sync(
                dst + (size_t)(m0 + wm * 64 + i * 16) * C_ + wn * 32 + j * 16,
                c[i][j], C_, wmma::mem_row_major);
}

// ---------------- fused MLP + log_softmax + Abits clear ------------------------------
__global__ void __launch_bounds__(128) k_mlp_lsm(
    const float* __restrict__ x,
    const float* __restrict__ fW,  const float* __restrict__ fb,
    const float* __restrict__ l0W, const float* __restrict__ l0b,
    const float* __restrict__ l1W, const float* __restrict__ l1b,
    float* __restrict__ out) {
    __shared__ float s1[16 * 256];     // concat input; later logits (16x64)
    __shared__ float sh[16 * 128];     // h1 then h2
    int r0 = blockIdx.x * 16, tid = threadIdx.x;  // 128 threads
    int lane = tid & 31;

    // stage 0: build concat [x | fused/deg] (split-K reduce + deg-div folded in)
    for (int i = tid; i < 16 * 128; i += 128) {
        int r = i >> 7, c = i & 127;
        float invd = 1.0f / (g_deg[r0 + r] + 1e-6f);
        float fs = 0.f;
        #pragma unroll
        for (int k = 0; k < KSPLIT; k++)
            fs += g_big[(size_t)k * (N_ * C_) + (size_t)(r0 + r) * C_ + c];
        s1[r * 256 + c]       = x[(size_t)(r0 + r) * 128 + c];
        s1[r * 256 + 128 + c] = fs * invd;
    }
    __syncthreads();

    // stage 1: h1 = concat @ fW + fb
    {
        float acc[16];
        float bb = fb[tid];
        #pragma unroll
        for (int r = 0; r < 16; r++) acc[r] = bb;
        for (int k = 0; k < 256; k++) {
            float wv = fW[k * 128 + tid];
            #pragma unroll
            for (int r = 0; r < 16; r++) acc[r] += s1[r * 256 + k] * wv;
        }
        #pragma unroll
        for (int r = 0; r < 16; r++) sh[r * 128 + tid] = acc[r];
    }
    __syncthreads();

    // stage 2: h2 = relu(h1 @ l0W + l0b)
    {
        float acc[16];
        float bb = l0b[tid];
        #pragma unroll
        for (int r = 0; r < 16; r++) acc[r] = bb;
        for (int k = 0; k < 128; k++) {
            float wv = l0W[k * 128 + tid];
            #pragma unroll
            for (int r = 0; r < 16; r++) acc[r] += sh[r * 128 + k] * wv;
        }
        __syncthreads();
        #pragma unroll
        for (int r = 0; r < 16; r++) sh[r * 128 + tid] = fmaxf(acc[r], 0.f);
    }
    __syncthreads();

    // stage 3: logits = h2 @ l1W + l1b -> s1 (as 16x64)
    {
        int col  = tid & 63;
        int half = tid >> 6;          // rows [0..7] / [8..15]
        float acc[8];
        float bb = l1b[col];
        #pragma unroll
        for (int q = 0; q < 8; q++) acc[q] = bb;
        for (int k = 0; k < 128; k++) {
            float wv = l1W[k * 64 + col];
            #pragma unroll
            for (int q = 0; q < 8; q++) acc[q] += sh[(half * 8 + q) * 128 + k] * wv;
        }
        #pragma unroll
        for (int q = 0; q < 8; q++) s1[(half * 8 + q) * 64 + col] = acc[q];
    }
    __syncthreads();

    // stage 4: log_softmax, warp w handles rows 4w..4w+3
    {
        int w = tid >> 5;
        #pragma unroll
        for (int rr = 0; rr < 4; rr++) {
            int r = w * 4 + rr;
            float v0 = s1[r * 64 + lane];
            float v1 = s1[r * 64 + 32 + lane];
            float m = fmaxf(v0, v1);
            #pragma unroll
            for (int o = 16; o; o >>= 1) m = fmaxf(m, __shfl_xor_sync(0xffffffffu, m, o));
            float s = expf(v0 - m) + expf(v1 - m);
            #pragma unroll
            for (int o = 16; o; o >>= 1) s += __shfl_xor_sync(0xffffffffu, s, o);
            float l = m + logf(s);
            out[(size_t)(r0 + r) * O_ + lane]      = v0 - l;
            out[(size_t)(r0 + r) * O_ + 32 + lane] = v1 - l;
        }
    }

    // stage 5: clear adjacency bitmask for next replay (statics start zeroed)
    {
        int base = (blockIdx.x * 128 + tid) * 16;
        uint4 z = make_uint4(0u, 0u, 0u, 0u);
        #pragma unroll
        for (int i = 0; i < 4; i++)
            *reinterpret_cast<uint4*>(&g_Abits[base + i * 4]) = z;
    }
}

// ---------------- launch ----------------
extern "C" void kernel_launch(void* const* d_in, const int* in_sizes, int n_in,
                              void* d_out, int out_size) {
    (void)in_sizes; (void)n_in; (void)out_size;
    const float* x     = (const float*)d_in[0];
    const int*   ei    = (const int*)d_in[1];     // int32 (JAX x64 disabled)
    const float* alpha = (const float*)d_in[2];
    const float* fW    = (const float*)d_in[3];
    const float* fb    = (const float*)d_in[4];
    const float* l0W   = (const float*)d_in[5];
    const float* l0b   = (const float*)d_in[6];
    const float* l1W   = (const float*)d_in[7];
    const float* l1b   = (const float*)d_in[8];
    float*       out   = (float*)d_out;

    void* p_big;
    cudaGetSymbolAddress(&p_big, g_big);

    // 1. scatter edges + rownorm (fused)
    k_pre<<<E_ / 256 + N_ * 32 / 256, 256>>>(ei, x);

    // 2. cosine sim, symmetric tiles only (bf16 tensor cores)
    k_gemm1_wmma<<<NTRI, 256>>>();

    // 3. mega: threefry (ALU) + topk (L2) + spmm1 (latency) — all independent, overlap
    k_big<<<TFB + N_ + N_ / 2, 256>>>((const float*)p_big, x);

    // 4. spmm2 + OR-topk/degree (independent of each other)
    k_mid<<<N_ / 2 + N_, 256>>>();

    // 5. aggT transpose (needs A2x)
    k_aggT<<<512, 256>>>(x, alpha);

    // 6. fused_raw = Mf @ agg (bf16 split-K x8, mask expanded from bits in-kernel)
    k_gemm2_wmma<<<dim3(KSPLIT, N_ / 128), 256>>>();

    // 7. fused MLP + log_softmax + Abits clear
    k_mlp_lsm<<<N_ / 16, 128>>>(x, fW, fb, l0W, l0b, l1W, l1b, out);
}

// round 17
// speedup vs baseline: 1.0068x; 1.0068x over previous
#include <cuda_runtime.h>
#include <cuda_bf16.h>
#include <mma.h>
using namespace nvcuda;

#define N_    4096
#define C_    128
#define H_    128
#define O_    64
#define E_    65536
#define WPR   128                 // 32-bit words per mask row (4096/32)
#define HALF_ 8388608             // N*N/2 for threefry pairing
#define TOPK_ 10
#define KSPLIT 8                  // gemm2 split-K factor
#define NT_   32                  // 128-tiles per dim
#define NTRI  528                 // NT_*(NT_+1)/2

// ---------------- scratch (static device globals; no allocation) ----------------
static __device__ unsigned       g_Abits[N_ * WPR];          // 2 MB adjacency bitmask
static __device__ unsigned       g_Mbits[N_ * WPR];          // 2 MB keep-mask bitmask
static __device__ float          g_big[(size_t)N_ * N_];     // 64 MB: sim; later gemm2 partials
static __device__ __nv_bfloat16  g_xnb[N_ * C_];             // xn in bf16
static __device__ __nv_bfloat16  g_aggT[(size_t)C_ * N_];    // agg^T bf16 [C][N]
static __device__ float          g_Ax [N_ * C_];
static __device__ float          g_A2x[N_ * C_];
static __device__ int            g_topk[N_ * TOPK_];
static __device__ float          g_deg[N_];

// ---------------- fused: scatter edges (blocks 0..255) + rownorm (256..767) ----------
// edge_index is int32 (JAX x64 disabled downgrades int64 -> int32), layout [2, E]
__global__ void __launch_bounds__(256) k_pre(const int* __restrict__ ei,
                                             const float* __restrict__ x) {
    if (blockIdx.x < E_ / 256) {
        int i = blockIdx.x * 256 + threadIdx.x;
        int s = ei[i];
        int d = ei[E_ + i];
        atomicOr(&g_Abits[s * WPR + (d >> 5)], 1u << (d & 31));
        return;
    }
    int g    = (blockIdx.x - E_ / 256) * 256 + threadIdx.x;
    int row  = g >> 5;
    int lane = g & 31;
    if (row >= N_) return;
    const float4* xr = reinterpret_cast<const float4*>(x + (size_t)row * C_);
    float4 v = xr[lane];
    float s = v.x * v.x + v.y * v.y + v.z * v.z + v.w * v.w;
    #pragma unroll
    for (int o = 16; o; o >>= 1) s += __shfl_xor_sync(0xffffffffu, s, o);
    float inv = 1.0f / (sqrtf(s) + 1e-8f);
    __nv_bfloat162 p0 = __floats2bfloat162_rn(v.x * inv, v.y * inv);
    __nv_bfloat162 p1 = __floats2bfloat162_rn(v.z * inv, v.w * inv);
    __nv_bfloat162* dst = reinterpret_cast<__nv_bfloat162*>(g_xnb + (size_t)row * C_ + lane * 4);
    dst[0] = p0;
    dst[1] = p1;
}

// ---------------- GEMM1 (symmetric): sim = xnb @ xnb^T, upper-tri tiles only ---------
#define G1PAD 16
__global__ void __launch_bounds__(256, 2) k_gemm1_wmma() {
    __shared__ __nv_bfloat16 As[128][128 + G1PAD];
    __shared__ __nv_bfloat16 Bs[128][128 + G1PAD];
    int tid = threadIdx.x;

    int idx = blockIdx.x;
    int bm = 0;
    while ((bm + 1) * NT_ - ((bm + 1) * bm) / 2 <= idx) bm++;
    int bn = bm + idx - (bm * NT_ - (bm * (bm - 1)) / 2);
    int m0 = bm * 128, n0 = bn * 128;

    #pragma unroll
    for (int it = 0; it < 8; it++) {
        int chunk = tid + 256 * it;
        int r = chunk >> 4, c8 = chunk & 15;
        *reinterpret_cast<uint4*>(&As[r][c8 * 8]) =
            *reinterpret_cast<const uint4*>(g_xnb + (size_t)(m0 + r) * C_ + c8 * 8);
        *reinterpret_cast<uint4*>(&Bs[r][c8 * 8]) =
            *reinterpret_cast<const uint4*>(g_xnb + (size_t)(n0 + r) * C_ + c8 * 8);
    }
    __syncthreads();

    int w = tid >> 5;
    int wm = w >> 2, wn = w & 3;
    wmma::fragment<wmma::accumulator, 16, 16, 16, float> c[4][2];
    #pragma unroll
    for (int i = 0; i < 4; i++)
        #pragma unroll
        for (int j = 0; j < 2; j++) wmma::fill_fragment(c[i][j], 0.0f);

    #pragma unroll
    for (int kk = 0; kk < 8; kk++) {
        wmma::fragment<wmma::matrix_a, 16, 16, 16, __nv_bfloat16, wmma::row_major> a[4];
        wmma::fragment<wmma::matrix_b, 16, 16, 16, __nv_bfloat16, wmma::col_major> b[2];
        #pragma unroll
        for (int i = 0; i < 4; i++)
            wmma::load_matrix_sync(a[i], &As[wm * 64 + i * 16][kk * 16], 128 + G1PAD);
        #pragma unroll
        for (int j = 0; j < 2; j++)
            wmma::load_matrix_sync(b[j], &Bs[wn * 32 + j * 16][kk * 16], 128 + G1PAD);
        #pragma unroll
        for (int i = 0; i < 4; i++)
            #pragma unroll
            for (int j = 0; j < 2; j++) wmma::mma_sync(c[i][j], a[i], b[j], c[i][j]);
    }
    #pragma unroll
    for (int i = 0; i < 4; i++)
        #pragma unroll
        for (int j = 0; j < 2; j++) {
            int mr = m0 + wm * 64 + i * 16;
            int nc = n0 + wn * 32 + j * 16;
            wmma::store_matrix_sync(g_big + (size_t)mr * N_ + nc, c[i][j], N_,
                                    wmma::mem_row_major);
            if (bm != bn)
                wmma::store_matrix_sync(g_big + (size_t)nc * N_ + mr, c[i][j], N_,
                                        wmma::mem_col_major);
        }
}

// ---------------- helpers ----------------
__device__ __forceinline__ unsigned ford(float f) {
    unsigned u = __float_as_uint(f);
    return (u & 0x80000000u) ? ~u : (u | 0x80000000u);
}

__device__ __forceinline__ void threefry(unsigned c0, unsigned c1, unsigned& o0, unsigned& o1) {
    const unsigned k0 = 0u, k1 = 42u, k2 = 0u ^ 42u ^ 0x1BD11BDAu;
    unsigned x0 = c0 + k0, x1 = c1 + k1;
    #define TF_R(r) { x0 += x1; x1 = __funnelshift_l(x1, x1, (r)); x1 ^= x0; }
    TF_R(13) TF_R(15) TF_R(26) TF_R(6)   x0 += k1; x1 += k2 + 1u;
    TF_R(17) TF_R(29) TF_R(16) TF_R(24)  x0 += k2; x1 += k0 + 2u;
    TF_R(13) TF_R(15) TF_R(26) TF_R(6)   x0 += k0; x1 += k1 + 3u;
    TF_R(17) TF_R(29) TF_R(16) TF_R(24)  x0 += k1; x1 += k2 + 4u;
    TF_R(13) TF_R(15) TF_R(26) TF_R(6)   x0 += k2; x1 += k0 + 5u;
    #undef TF_R
    o0 = x0; o1 = x1;
}

__device__ __forceinline__ unsigned long long umax64(unsigned long long a, unsigned long long b) {
    return a > b ? a : b;
}

// ---------------- fused: topk (blocks 0..4095, two-level) + threefry (rest) ----------
__global__ void __launch_bounds__(256) k_topk_tf(const float* __restrict__ sim) {
    if (blockIdx.x >= N_) {
        // ---- threefry: ALU-bound, back-fills as topk blocks drain ----
        int t = (blockIdx.x - N_) * 256 + threadIdx.x;   // 0 .. HALF_-1
        unsigned o0, o1;
        threefry((unsigned)t, (unsigned)t + (unsigned)HALF_, o0, o1);
        unsigned m0 = __ballot_sync(0xffffffffu, !(o0 >> 31));
        unsigned m1 = __ballot_sync(0xffffffffu, !(o1 >> 31));
        int lane = threadIdx.x & 31;
        int wbase = t >> 5;
        if (lane == 0)      g_Mbits[wbase] = m0;
        else if (lane == 1) g_Mbits[(HALF_ >> 5) + wbase] = m1;
        return;
    }
    // ---- topk: per-warp top-10 in registers, then single-warp merge of 80 ----
    __shared__ unsigned long long cand[8 * TOPK_];
    int row  = blockIdx.x;
    int tid  = threadIdx.x;          // 256 = 8 warps
    int w    = tid >> 5;
    int lane = tid & 31;

    unsigned long long key[16];
    #pragma unroll
    for (int i = 0; i < 16; i++) {
        int j = w * 512 + i * 32 + lane;
        float v = sim[(size_t)row * N_ + j];
        key[i] = ((unsigned long long)ford(v) << 32) | (unsigned)(N_ - 1 - j);
    }
    #pragma unroll
    for (int p = 0; p < TOPK_; p++) {
        unsigned long long m = 0ull;
        #pragma unroll
        for (int i = 0; i < 16; i++) m = umax64(m, key[i]);
        #pragma unroll
        for (int o = 16; o; o >>= 1)
            m = umax64(m, __shfl_xor_sync(0xffffffffu, m, o));
        if (lane == 0) cand[w * TOPK_ + p] = m;
        #pragma unroll
        for (int i = 0; i < 16; i++) if (key[i] == m) key[i] = 0ull;  // unique keys
    }
    __syncthreads();
    if (w == 0) {
        unsigned long long c0 = cand[lane];                            // 0..31
        unsigned long long c1 = cand[lane + 32];                       // 32..63
        unsigned long long c2 = (lane < 16) ? cand[lane + 64] : 0ull;  // 64..79
        #pragma unroll
        for (int p = 0; p < TOPK_; p++) {
            unsigned long long m = umax64(c0, umax64(c1, c2));
            #pragma unroll
            for (int o = 16; o; o >>= 1)
                m = umax64(m, __shfl_xor_sync(0xffffffffu, m, o));
            if (lane == 0) g_topk[row * TOPK_ + p] = (N_ - 1) - (int)(m & 0xffffffffull);
            if (c0 == m) c0 = 0ull;
            if (c1 == m) c1 = 0ull;
            if (c2 == m) c2 = 0ull;
        }
    }
}

// ---------------- sparse A*V: decode neighbor list, then ILP-4 accumulate ------------
__global__ void __launch_bounds__(128) k_spmm(const unsigned* __restrict__ bits,
                                              const float* __restrict__ V,
                                              float* __restrict__ out) {
    __shared__ unsigned short nbr[N_];
    __shared__ int wsum[4];
    int row = blockIdx.x, tid = threadIdx.x;   // 128 threads = 128 words = 128 cols
    int lane = tid & 31, w = tid >> 5;

    unsigned word = bits[row * WPR + tid];
    int cnt = __popc(word);
    int inc = cnt;
    #pragma unroll
    for (int o = 1; o < 32; o <<= 1) {
        int v = __shfl_up_sync(0xffffffffu, inc, o);
        if (lane >= o) inc += v;
    }
    if (lane == 31) wsum[w] = inc;
    __syncthreads();
    int base = 0;
    #pragma unroll
    for (int i = 0; i < 4; i++) if (i < w) base += wsum[i];
    int off = base + inc - cnt;
    unsigned b = word;
    while (b) {
        int t = __ffs(b) - 1;
        b &= b - 1;
        nbr[off++] = (unsigned short)((tid << 5) + t);
    }
    int nn = wsum[0] + wsum[1] + wsum[2] + wsum[3];
    __syncthreads();

    float a0 = 0.f, a1 = 0.f, a2 = 0.f, a3 = 0.f;
    int i = 0;
    for (; i + 4 <= nn; i += 4) {
        int j0 = nbr[i], j1 = nbr[i + 1], j2 = nbr[i + 2], j3 = nbr[i + 3];
        a0 += V[(size_t)j0 * C_ + tid];
        a1 += V[(size_t)j1 * C_ + tid];
        a2 += V[(size_t)j2 * C_ + tid];
        a3 += V[(size_t)j3 * C_ + tid];
    }
    for (; i < nn; i++) a0 += V[(size_t)nbr[i] * C_ + tid];
    out[(size_t)row * C_ + tid] = (a0 + a1) + (a2 + a3);
}

// ---------------- fused: aggT transpose (blocks 0..511) + or_deg (512..4607) ---------
__global__ void __launch_bounds__(256) k_aggT_ordeg(const float* __restrict__ x,
                                                    const float* __restrict__ alpha) {
    if (blockIdx.x < 512) {
        __shared__ float t[32][33];
        int bx = blockIdx.x & 3, by = blockIdx.x >> 2;     // (C_/32, N_/32)
        int c0 = bx * 32, r0 = by * 32;
        int tx = threadIdx.x & 31, ty = threadIdx.x >> 5;  // 32 x 8
        float a0 = __ldg(&alpha[0]), a1 = __ldg(&alpha[1]), a2 = __ldg(&alpha[2]);
        #pragma unroll
        for (int i = 0; i < 4; i++) {
            size_t idx = (size_t)(r0 + ty + 8 * i) * C_ + c0 + tx;
            t[ty + 8 * i][tx] = a0 * x[idx] + a1 * g_Ax[idx] + a2 * g_A2x[idx];
        }
        __syncthreads();
        #pragma unroll
        for (int i = 0; i < 4; i++)
            g_aggT[(size_t)(c0 + ty + 8 * i) * N_ + r0 + tx] =
                __float2bfloat16(t[tx][ty + 8 * i]);
        return;
    }
    // or_deg: OR top-k bits into Mbits + row degree (no atomics); first 128 threads
    __shared__ int wsum[4];
    int row = blockIdx.x - 512, tid = threadIdx.x;
    if (tid < 128) {
        int lane = tid & 31, w = tid >> 5;
        unsigned wd = g_Mbits[row * WPR + tid];
        #pragma unroll
        for (int p = 0; p < TOPK_; p++) {
            int j = g_topk[row * TOPK_ + p];
            if ((j >> 5) == tid) wd |= 1u << (j & 31);
        }
        g_Mbits[row * WPR + tid] = wd;
        int c = __popc(wd);
        #pragma unroll
        for (int o = 16; o; o >>= 1) c += __shfl_xor_sync(0xffffffffu, c, o);
        if (lane == 0) wsum[w] = c;
    }
    __syncthreads();
    if (tid == 0) g_deg[row] = (float)(wsum[0] + wsum[1] + wsum[2] + wsum[3]);
}

// ---------------- GEMM2 split-K with on-the-fly bf16 mask expansion ------------------
#define G2PAD 16
__global__ void __launch_bounds__(256, 2) k_gemm2_wmma() {
    __shared__ __nv_bfloat16 As[128][64 + G2PAD];
    __shared__ __nv_bfloat16 Bs[128][64 + G2PAD];
    int tid = threadIdx.x;
    int split = blockIdx.x;
    int m0 = blockIdx.y * 128;
    int kbase = split * (N_ / KSPLIT);
    int w = tid >> 5;
    int wm = w >> 2, wn = w & 3;
    int er = tid >> 1, eh = tid & 1;

    wmma::fragment<wmma::accumulator, 16, 16, 16, float> c[4][2];
    #pragma unroll
    for (int i = 0; i < 4; i++)
        #pragma unroll
        for (int j = 0; j < 2; j++) wmma::fill_fragment(c[i][j], 0.0f);

    for (int k0 = kbase; k0 < kbase + N_ / KSPLIT; k0 += 64) {
        {
            unsigned wd = g_Mbits[(m0 + er) * WPR + (k0 >> 5) + eh];
            __nv_bfloat16* dst = &As[er][eh * 32];
            #pragma unroll
            for (int gq = 0; gq < 4; gq++) {
                uint4 v;
                unsigned b = wd >> (gq * 8);
                v.x = ((b      & 1u) ? 0x3F80u : 0u) | (((b >> 1) & 1u) ? 0x3F800000u : 0u);
                v.y = (((b >> 2) & 1u) ? 0x3F80u : 0u) | (((b >> 3) & 1u) ? 0x3F800000u : 0u);
                v.z = (((b >> 4) & 1u) ? 0x3F80u : 0u) | (((b >> 5) & 1u) ? 0x3F800000u : 0u);
                v.w = (((b >> 6) & 1u) ? 0x3F80u : 0u) | (((b >> 7) & 1u) ? 0x3F800000u : 0u);
                reinterpret_cast<uint4*>(dst)[gq] = v;
            }
        }
        #pragma unroll
        for (int it = 0; it < 4; it++) {
            int chunk = tid + 256 * it;
            int r = chunk >> 3, c8 = chunk & 7;
            *reinterpret_cast<uint4*>(&Bs[r][c8 * 8]) =
                *reinterpret_cast<const uint4*>(g_aggT + (size_t)r * N_ + k0 + c8 * 8);
        }
        __syncthreads();
        #pragma unroll
        for (int kk = 0; kk < 4; kk++) {
            wmma::fragment<wmma::matrix_a, 16, 16, 16, __nv_bfloat16, wmma::row_major> a[4];
            wmma::fragment<wmma::matrix_b, 16, 16, 16, __nv_bfloat16, wmma::col_major> b[2];
            #pragma unroll
            for (int i = 0; i < 4; i++)
                wmma::load_matrix_sync(a[i], &As[wm * 64 + i * 16][kk * 16], 64 + G2PAD);
            #pragma unroll
            for (int j = 0; j < 2; j++)
                wmma::load_matrix_sync(b[j], &Bs[wn * 32 + j * 16][kk * 16], 64 + G2PAD);
            #pragma unroll
            for (int i = 0; i < 4; i++)
                #pragma unroll
                for (int j = 0; j < 2; j++) wmma::mma_sync(c[i][j], a[i], b[j], c[i][j]);
        }
        __syncthreads();
    }
    float* dst = g_big + (size_t)split * (N_ * C_);
    #pragma unroll
    for (int i = 0; i < 4; i++)
        #pragma unroll
        for (int j = 0; j < 2; j++)
            wmma::store_matrix_sync(
                dst + (size_t)(m0 + wm * 64 + i * 16) * C_ + wn * 32 + j * 16,
                c[i][j], C_, wmma::mem_row_major);
}

// ---------------- fused MLP + log_softmax + Abits clear ------------------------------
__global__ void __launch_bounds__(128) k_mlp_lsm(
    const float* __restrict__ x,
    const float* __restrict__ fW,  const float* __restrict__ fb,
    const float* __restrict__ l0W, const float* __restrict__ l0b,
    const float* __restrict__ l1W, const float* __restrict__ l1b,
    float* __restrict__ out) {
    __shared__ float s1[16 * 256];     // concat input; later logits (16x64)
    __shared__ float sh[16 * 128];     // h1 then h2
    int r0 = blockIdx.x * 16, tid = threadIdx.x;  // 128 threads
    int lane = tid & 31;

    // stage 0: build concat [x | fused/deg] (split-K reduce + deg-div folded in)
    for (int i = tid; i < 16 * 128; i += 128) {
        int r = i >> 7, c = i & 127;
        float invd = 1.0f / (g_deg[r0 + r] + 1e-6f);
        float fs = 0.f;
        #pragma unroll
        for (int k = 0; k < KSPLIT; k++)
            fs += g_big[(size_t)k * (N_ * C_) + (size_t)(r0 + r) * C_ + c];
        s1[r * 256 + c]       = x[(size_t)(r0 + r) * 128 + c];
        s1[r * 256 + 128 + c] = fs * invd;
    }
    __syncthreads();

    // stage 1: h1 = concat @ fW + fb
    {
        float acc[16];
        float bb = fb[tid];
        #pragma unroll
        for (int r = 0; r < 16; r++) acc[r] = bb;
        for (int k = 0; k < 256; k++) {
            float wv = fW[k * 128 + tid];
            #pragma unroll
            for (int r = 0; r < 16; r++) acc[r] += s1[r * 256 + k] * wv;
        }
        #pragma unroll
        for (int r = 0; r < 16; r++) sh[r * 128 + tid] = acc[r];
    }
    __syncthreads();

    // stage 2: h2 = relu(h1 @ l0W + l0b)
    {
        float acc[16];
        float bb = l0b[tid];
        #pragma unroll
        for (int r = 0; r < 16; r++) acc[r] = bb;
        for (int k = 0; k < 128; k++) {
            float wv = l0W[k * 128 + tid];
            #pragma unroll
            for (int r = 0; r < 16; r++) acc[r] += sh[r * 128 + k] * wv;
        }
        __syncthreads();
        #pragma unroll
        for (int r = 0; r < 16; r++) sh[r * 128 + tid] = fmaxf(acc[r], 0.f);
    }
    __syncthreads();

    // stage 3: logits = h2 @ l1W + l1b -> s1 (as 16x64)
    {
        int col  = tid & 63;
        int half = tid >> 6;          // rows [0..7] / [8..15]
        float acc[8];
        float bb = l1b[col];
        #pragma unroll
        for (int q = 0; q < 8; q++) acc[q] = bb;
        for (int k = 0; k < 128; k++) {
            float wv = l1W[k * 64 + col];
            #pragma unroll
            for (int q = 0; q < 8; q++) acc[q] += sh[(half * 8 + q) * 128 + k] * wv;
        }
        #pragma unroll
        for (int q = 0; q < 8; q++) s1[(half * 8 + q) * 64 + col] = acc[q];
    }
    __syncthreads();

    // stage 4: log_softmax, warp w handles rows 4w..4w+3
    {
        int w = tid >> 5;
        #pragma unroll
        for (int rr = 0; rr < 4; rr++) {
            int r = w * 4 + rr;
            float v0 = s1[r * 64 + lane];
            float v1 = s1[r * 64 + 32 + lane];
            float m = fmaxf(v0, v1);
            #pragma unroll
            for (int o = 16; o; o >>= 1) m = fmaxf(m, __shfl_xor_sync(0xffffffffu, m, o));
            float s = expf(v0 - m) + expf(v1 - m);
            #pragma unroll
            for (int o = 16; o; o >>= 1) s += __shfl_xor_sync(0xffffffffu, s, o);
            float l = m + logf(s);
            out[(size_t)(r0 + r) * O_ + lane]      = v0 - l;
            out[(size_t)(r0 + r) * O_ + 32 + lane] = v1 - l;
        }
    }

    // stage 5: clear adjacency bitmask for next replay (statics start zeroed)
    {
        int base = (blockIdx.x * 128 + tid) * 16;
        uint4 z = make_uint4(0u, 0u, 0u, 0u);
        #pragma unroll
        for (int i = 0; i < 4; i++)
            *reinterpret_cast<uint4*>(&g_Abits[base + i * 4]) = z;
    }
}

// ---------------- launch ----------------
extern "C" void kernel_launch(void* const* d_in, const int* in_sizes, int n_in,
                              void* d_out, int out_size) {
    (void)in_sizes; (void)n_in; (void)out_size;
    const float* x     = (const float*)d_in[0];
    const int*   ei    = (const int*)d_in[1];     // int32 (JAX x64 disabled)
    const float* alpha = (const float*)d_in[2];
    const float* fW    = (const float*)d_in[3];
    const float* fb    = (const float*)d_in[4];
    const float* l0W   = (const float*)d_in[5];
    const float* l0b   = (const float*)d_in[6];
    const float* l1W   = (const float*)d_in[7];
    const float* l1b   = (const float*)d_in[8];
    float*       out   = (float*)d_out;

    void *p_big, *p_Abits, *p_Ax, *p_A2x;
    cudaGetSymbolAddress(&p_big,   g_big);
    cudaGetSymbolAddress(&p_Abits, g_Abits);
    cudaGetSymbolAddress(&p_Ax,    g_Ax);
    cudaGetSymbolAddress(&p_A2x,   g_A2x);

    // 1. scatter edges + rownorm (fused)
    k_pre<<<E_ / 256 + N_ * 32 / 256, 256>>>(ei, x);

    // 2. cosine sim, symmetric tiles only (bf16 tensor cores)
    k_gemm1_wmma<<<NTRI, 256>>>();

    // 3. hop features
    k_spmm<<<N_, 128>>>((const unsigned*)p_Abits, x, (float*)p_Ax);
    k_spmm<<<N_, 128>>>((const unsigned*)p_Abits, (const float*)p_Ax, (float*)p_A2x);

    // 4. fused: topk (two-level, mem-bound, first) + threefry (ALU-bound, back-fill)
    k_topk_tf<<<N_ + HALF_ / 256, 256>>>((const float*)p_big);

    // 5. fused: aggT transpose + OR-topk/degree
    k_aggT_ordeg<<<512 + N_, 256>>>(x, alpha);

    // 6. fused_raw = Mf @ agg (bf16 split-K x8, mask expanded from bits in-kernel)
    k_gemm2_wmma<<<dim3(KSPLIT, N_ / 128), 256>>>();

    // 7. fused MLP + log_softmax + Abits clear
    k_mlp_lsm<<<N_ / 16, 128>>>(x, fW, fb, l0W, l0b, l1W, l1b, out);
}